// round 7
// baseline (speedup 1.0000x reference)
#include <cuda_runtime.h>

// GraphAttention_14740327760460 — FINAL
//
// Dead-code analysis of the reference (verified rel_err=0.0, R1-R6):
//   Wh2 = h @ W_out is [N, 1]; log_softmax(out, axis=1) over a singleton
//   axis is x - logsumexp(x) = 0 exactly for all finite x. adj includes
//   self-loops, so every masked-softmax row is a valid distribution and
//   all intermediates are finite. The reference output is identically
//   0.0f — the entire attention pipeline is dead code w.r.t. the output.
//
// Optimization ledger (all levers tested, predict->verify each round):
//   R2: graph memset node is ~0.3us SLOWER than a kernel node -> kernel node.
//   R1/R3/R4: grid shape and store width have NO effect on kernel time
//     (3.17-3.46us) — it is pure launch overhead. DRAM=0%, L2=0.3%.
//   R4/R5/R6: identical binary -> e2e 4.61/5.25/4.61us: residual spread is
//     harness/replay noise, decorrelated from the kernel body.
//   D2D memcpy node untested by choice: same CE-class path that lost in R2,
//     plus a source read — predicted regression.
//
// Floor: modal e2e ~4.6us, kernel ~3.3us, single-kernel-node graph-replay
// bound. Kernel: 4 blocks x 256 threads, one STG.128 each, exact 16KB
// coverage, zero control flow, regs=16.

__global__ void __launch_bounds__(256, 1)
GraphAttention_14740327760460_zero4(float4* __restrict__ out) {
    unsigned idx = blockIdx.x * 256u + threadIdx.x;
    out[idx] = make_float4(0.f, 0.f, 0.f, 0.f);
}

__global__ void GraphAttention_14740327760460_zero_generic(float* __restrict__ out, int n) {
    int i = blockIdx.x * blockDim.x + threadIdx.x;
    if (i < n) out[i] = 0.0f;
}

extern "C" void kernel_launch(void* const* d_in, const int* in_sizes, int n_in,
                              void* d_out, int out_size) {
    (void)d_in; (void)in_sizes; (void)n_in;
    if (out_size == 4096) {
        // 4096 floats = 1024 float4 = 4 blocks * 256 threads
        GraphAttention_14740327760460_zero4<<<4, 256>>>((float4*)d_out);
    } else {
        int threads = 256;
        int blocks = (out_size + threads - 1) / threads;
        GraphAttention_14740327760460_zero_generic<<<blocks, threads>>>((float*)d_out, out_size);
    }
}

// round 8
// speedup vs baseline: 1.0486x; 1.0486x over previous
#include <cuda_runtime.h>

// GraphAttention_14740327760460 — FINAL (held config; floor characterized)
//
// Dead-code analysis of the reference (verified rel_err=0.0, R1-R7):
//   Wh2 = h @ W_out is [N, 1]; log_softmax(out, axis=1) over a singleton
//   axis is x - logsumexp(x) = 0 exactly for all finite x. adj includes
//   self-loops, so every masked-softmax row is a valid distribution and
//   all intermediates are finite. The reference output is identically
//   0.0f — the full attention pipeline is dead code w.r.t. the output.
//
// Optimization ledger (predict->verify each round):
//   R2: graph memset node ~0.3us SLOWER than a kernel node -> kernel node.
//   R1/R3/R4: grid shape and store width have NO effect on kernel time
//     (3.17-3.52us) — pure launch overhead. DRAM=0%, L2=0.3%, pipes=0%.
//   R4-R7: identical binary -> e2e {4.61, 5.25, 4.61, 4.83}us: spread is
//     harness/replay noise, decorrelated from the kernel body.
//   Rejected on theory: D2D memcpy node (CE-path class already lost in R2,
//     plus a source read), node splitting (adds replay overhead).
//
// Floor: e2e mean ~4.8us (min 4.58, sigma ~0.24), kernel ~3.3us —
// single-kernel-node graph-replay bound. Kernel: 4 blocks x 256 threads,
// one STG.128 each, exact 16KB coverage, zero control flow, regs=16.

__global__ void __launch_bounds__(256, 1)
GraphAttention_14740327760460_zero4(float4* __restrict__ out) {
    unsigned idx = blockIdx.x * 256u + threadIdx.x;
    out[idx] = make_float4(0.f, 0.f, 0.f, 0.f);
}

__global__ void GraphAttention_14740327760460_zero_generic(float* __restrict__ out, int n) {
    int i = blockIdx.x * blockDim.x + threadIdx.x;
    if (i < n) out[i] = 0.0f;
}

extern "C" void kernel_launch(void* const* d_in, const int* in_sizes, int n_in,
                              void* d_out, int out_size) {
    (void)d_in; (void)in_sizes; (void)n_in;
    if (out_size == 4096) {
        // 4096 floats = 1024 float4 = 4 blocks * 256 threads
        GraphAttention_14740327760460_zero4<<<4, 256>>>((float4*)d_out);
    } else {
        int threads = 256;
        int blocks = (out_size + threads - 1) / threads;
        GraphAttention_14740327760460_zero_generic<<<blocks, threads>>>((float*)d_out, out_size);
    }
}

// round 9
// speedup vs baseline: 1.0559x; 1.0070x over previous
#include <cuda_runtime.h>

// GraphAttention_14740327760460 — FINAL (floor reached; config held)
//
// Dead-code analysis of the reference (verified rel_err=0.0, R1-R8):
//   Wh2 = h @ W_out is [N, 1]; log_softmax(out, axis=1) over a singleton
//   axis is x - logsumexp(x) = 0 exactly for all finite x. adj includes
//   self-loops, so every masked-softmax row is a valid distribution and
//   all intermediates are finite. The reference output is identically
//   0.0f — the full 17-GFLOP attention pipeline is dead code w.r.t. the
//   returned tensor. The minimal correct computation contains no math.
//
// Optimization ledger (predict->verify each round):
//   R2: graph memset node ~0.3us SLOWER than a kernel node -> kernel node.
//   R1/R3/R4: grid shape and store width have NO effect on kernel GPU time
//     (3.17-3.52us) — pure launch overhead. DRAM=0%, L2=0.3%, pipes=0%.
//   R4-R8: identical binary -> e2e {4.61, 5.25, 4.61, 4.83, 4.61}us:
//     spread is harness/replay noise, decorrelated from the kernel body.
//   Rejected on theory: D2D memcpy node (CE-path class lost in R2 plus a
//     source read), node splitting (adds replay overhead).
//
// Floor: e2e mode 4.61us (min 4.58, sigma ~0.24), kernel ~3.3us —
// single-kernel-node graph-replay bound. Kernel: 4 blocks x 256 threads,
// one STG.128 each, exact 16KB coverage, zero control flow, regs=16.

__global__ void __launch_bounds__(256, 1)
GraphAttention_14740327760460_zero4(float4* __restrict__ out) {
    unsigned idx = blockIdx.x * 256u + threadIdx.x;
    out[idx] = make_float4(0.f, 0.f, 0.f, 0.f);
}

__global__ void GraphAttention_14740327760460_zero_generic(float* __restrict__ out, int n) {
    int i = blockIdx.x * blockDim.x + threadIdx.x;
    if (i < n) out[i] = 0.0f;
}

extern "C" void kernel_launch(void* const* d_in, const int* in_sizes, int n_in,
                              void* d_out, int out_size) {
    (void)d_in; (void)in_sizes; (void)n_in;
    if (out_size == 4096) {
        // 4096 floats = 1024 float4 = 4 blocks * 256 threads
        GraphAttention_14740327760460_zero4<<<4, 256>>>((float4*)d_out);
    } else {
        int threads = 256;
        int blocks = (out_size + threads - 1) / threads;
        GraphAttention_14740327760460_zero_generic<<<blocks, threads>>>((float*)d_out, out_size);
    }
}